// round 8
// baseline (speedup 1.0000x reference)
#include <cuda_runtime.h>
#include <cstdint>

#define BATCH 16
#define NCLS 7
#define HH 368
#define WW 640
#define NSEG (BATCH * 6)

// Per-(b, class, row, warp) packed stats, padded to 8 words/row (32B) for
// aligned uint4 reads. Word: bits[0:10)=min col, [10:20)=max col,
// [20:31)=count (0 means empty for this class in this warp's 128 cols).
// Only warps 0..4 are written; combine ignores slots 5..7.
__device__ unsigned g_row5[NSEG * HH * 8];
__device__ float g_part[NSEG];
__device__ int g_done = 0;

__device__ __forceinline__ int atom_add_acqrel1(int* p) {
    int old;
    asm volatile("atom.acq_rel.gpu.global.add.s32 %0, [%1], 1;"
                 : "=r"(old) : "l"(p) : "memory");
    return old;
}

// -------------------------------------------------------------------------
// Kernel 1 (unchanged from R7): per-pixel class via soft-argmax ->
// per-WARP per-class (min,max,count) stored directly; no smem, no barrier.
// -------------------------------------------------------------------------
__device__ __forceinline__ int pix_class(const float l[7]) {
    float e0 = __expf(l[0]);
    float e1 = __expf(l[1]);
    float e2 = __expf(l[2]);
    float e3 = __expf(l[3]);
    float e4 = __expf(l[4]);
    float e5 = __expf(l[5]);
    float e6 = __expf(l[6]);
    float den = ((e0 + e1) + (e2 + e3)) + ((e4 + e5) + e6);
    float num = e1;
    num = fmaf(2.0f, e2, num);
    num = fmaf(3.0f, e3, num);
    num = fmaf(4.0f, e4, num);
    num = fmaf(5.0f, e5, num);
    num = fmaf(6.0f, e6, num);
    // num/den in [0,6]; truncation == floor for non-negative values.
    float r = __fdividef(num, den);
    return (int)r;
}

__global__ __launch_bounds__(160) void k_rowstats(const float* __restrict__ logits) {
    const int row  = blockIdx.x;
    const int b    = blockIdx.y;
    const int t    = threadIdx.x;
    const int lane = t & 31;
    const int warp = t >> 5;
    const int col0 = t << 2;   // 4 pixels per thread

    float4 v[NCLS];
#pragma unroll
    for (int c = 0; c < NCLS; c++) {
        const float* p = logits + (((size_t)b * NCLS + c) * HH + row) * WW + col0;
        v[c] = *reinterpret_cast<const float4*>(p);
    }

    int k0, k1, k2, k3;
    {
        float l[7];
#pragma unroll
        for (int c = 0; c < NCLS; c++) l[c] = v[c].x;
        k0 = pix_class(l);
#pragma unroll
        for (int c = 0; c < NCLS; c++) l[c] = v[c].y;
        k1 = pix_class(l);
#pragma unroll
        for (int c = 0; c < NCLS; c++) l[c] = v[c].z;
        k2 = pix_class(l);
#pragma unroll
        for (int c = 0; c < NCLS; c++) l[c] = v[c].w;
        k3 = pix_class(l);
    }

    // One-hot bitboard: byte j holds (1 << class_of_pixel_j).
    const unsigned B = (1u << k0) | (1u << (k1 + 8)) | (1u << (k2 + 16)) | (1u << (k3 + 24));

    unsigned mypk = 0;  // lane c-1 keeps class c's packed stats

#pragma unroll
    for (int c = 1; c <= 6; c++) {
        unsigned m = (B >> c) & 0x01010101u;  // bit 8*j set iff pixel j is class c
        int cnt = __popc(m);
        int mnl = m ? col0 + ((__ffs(m) - 1) >> 3) : 0x7fffffff;
        int mxl = m ? col0 + ((31 - __clz(m)) >> 3) : -1;
        int wmn = __reduce_min_sync(0xffffffffu, mnl);
        int wmx = __reduce_max_sync(0xffffffffu, mxl);
        int wct = __reduce_add_sync(0xffffffffu, cnt);
        if (lane == c - 1) {
            mypk = (wct == 0) ? 0u
                 : ((unsigned)wmn | ((unsigned)wmx << 10) | ((unsigned)wct << 20));
        }
    }

    if (lane < 6) {
        g_row5[(((b * 6 + lane) * HH) + row) * 8 + warp] = mypk;
    }
}

// -------------------------------------------------------------------------
// Kernel 2: one block per segment, 128 threads (4 warps). Thread t owns
// contiguous rows [3t, 3t+3): 6 independent uint4 loads up-front, fold the
// 5 warp-slots per row, merge the 3 rows locally in order. Warp tree
// (5 steps) then a single 4-entry cross-warp merge. Publication of g_part
// is ordered by an acq_rel atomic (no threadfence). Last block sums the 96
// partials in fixed order.
// -------------------------------------------------------------------------
__global__ __launch_bounds__(128) void k_combine(float* __restrict__ out) {
    const int seg  = blockIdx.x;
    const int t    = threadIdx.x;
    const int lane = t & 31;
    const int w    = t >> 5;

    int valid = 0, cnt = 0, S = 0;
    int fcol = 0, frow = 0, lcol = 0, lrow = 0;

    const int r0 = 3 * t;
#pragma unroll
    for (int i = 0; i < 3; i++) {
        const int r = r0 + i;
        if (r < HH) {
            const uint4* p = reinterpret_cast<const uint4*>(&g_row5[(seg * HH + r) * 8]);
            uint4 a = p[0];
            uint4 bq = p[1];
            unsigned pks[5] = {a.x, a.y, a.z, a.w, bq.x};
            int rc = 0, mnv = 0x7fffffff, mxv = -1;
#pragma unroll
            for (int s = 0; s < 5; s++) {
                unsigned pk = pks[s];
                int c = pk >> 20;
                if (c) {
                    rc += c;
                    mnv = min(mnv, (int)(pk & 1023));
                    mxv = max(mxv, (int)((pk >> 10) & 1023));
                }
            }
            if (rc) {
                if (valid) {
                    S += abs((mnv - r) - (lcol - lrow));
                } else {
                    fcol = mnv; frow = r; valid = 1;
                }
                S += mxv - mnv;
                lcol = mxv; lrow = r; cnt += rc;
            }
        }
    }

    // Ordered warp tree: lane absorbs the segment from lane+off (its right).
#pragma unroll
    for (int off = 1; off < 32; off <<= 1) {
        int ov  = __shfl_down_sync(0xffffffffu, valid, off);
        int oc  = __shfl_down_sync(0xffffffffu, cnt, off);
        int oS  = __shfl_down_sync(0xffffffffu, S, off);
        int ofc = __shfl_down_sync(0xffffffffu, fcol, off);
        int ofr = __shfl_down_sync(0xffffffffu, frow, off);
        int olc = __shfl_down_sync(0xffffffffu, lcol, off);
        int olr = __shfl_down_sync(0xffffffffu, lrow, off);
        if ((lane & (2 * off - 1)) == 0 && ov) {
            if (valid) {
                S += oS + abs((ofc - ofr) - (lcol - lrow));
            } else {
                S = oS; fcol = ofc; frow = ofr; valid = 1;
            }
            cnt += oc;
            lcol = olc; lrow = olr;
        }
    }

    // Cross-warp merge: 4 warp results.
    __shared__ int sv[4], sc[4], sS[4], sfc[4], sfr[4], slc[4], slr[4];
    if (lane == 0) {
        sv[w] = valid; sc[w] = cnt; sS[w] = S;
        sfc[w] = fcol; sfr[w] = frow; slc[w] = lcol; slr[w] = lrow;
    }
    __syncthreads();

    if (w == 0) {
        if (lane < 4) {
            valid = sv[lane]; cnt = sc[lane]; S = sS[lane];
            fcol = sfc[lane]; frow = sfr[lane]; lcol = slc[lane]; lrow = slr[lane];
        } else {
            valid = 0; cnt = 0; S = 0; fcol = frow = lcol = lrow = 0;
        }
#pragma unroll
        for (int off = 1; off < 4; off <<= 1) {
            int ov  = __shfl_down_sync(0xffffffffu, valid, off);
            int oc  = __shfl_down_sync(0xffffffffu, cnt, off);
            int oS  = __shfl_down_sync(0xffffffffu, S, off);
            int ofc = __shfl_down_sync(0xffffffffu, fcol, off);
            int ofr = __shfl_down_sync(0xffffffffu, frow, off);
            int olc = __shfl_down_sync(0xffffffffu, lcol, off);
            int olr = __shfl_down_sync(0xffffffffu, lrow, off);
            if ((lane & (2 * off - 1)) == 0 && ov) {
                if (valid) {
                    S += oS + abs((ofc - ofr) - (lcol - lrow));
                } else {
                    S = oS; fcol = ofc; frow = ofr; valid = 1;
                }
                cnt += oc;
                lcol = olc; lrow = olr;
            }
        }
        if (lane == 0) {
            float loss = 0.0f;
            if (cnt >= 2) {
                loss = ((float)S / (float)(cnt - 1)) / (float)(cnt + 1);
            }
            g_part[seg] = loss;

            // Publish + elect finisher in one acq_rel atomic (no threadfence).
            int old = atom_add_acqrel1(&g_done);
            if (old == NSEG - 1) {
                float s = 0.0f;
#pragma unroll
                for (int i = 0; i < NSEG; i++) s += __ldcg(&g_part[i]);  // fixed order
                out[0] = s;
                g_done = 0;  // reset for next graph replay
            }
        }
    }
}

extern "C" void kernel_launch(void* const* d_in, const int* in_sizes, int n_in,
                              void* d_out, int out_size) {
    const float* logits = (const float*)d_in[0];
    // d_in[1] (labels) is unused by the reference computation.
    dim3 g1(HH, BATCH);
    k_rowstats<<<g1, 160>>>(logits);
    k_combine<<<NSEG, 128>>>((float*)d_out);
}

// round 9
// speedup vs baseline: 1.0918x; 1.0918x over previous
#include <cuda_runtime.h>
#include <cstdint>

#define BATCH 16
#define NCLS 7
#define HH 368
#define WW 640
#define NSEG (BATCH * 6)

// Per-(b, class, row, warp) packed stats, padded to 8 words/row (32B) for
// aligned uint4 reads. Word: bits[0:10)=min col, [10:20)=max col,
// [20:31)=count (0 means empty for this class in this warp's 128 cols).
// Only warps 0..4 are written; slots 5..7 stay zero (never written).
__device__ unsigned g_row5[NSEG * HH * 8];
__device__ float g_part[NSEG];

// -------------------------------------------------------------------------
// Kernel 1 (unchanged from R7 best): per-pixel class via soft-argmax ->
// per-WARP per-class (min,max,count) stored directly; no smem, no barrier.
// One block per (row, batch); 160 threads, 4 consecutive pixels each.
// -------------------------------------------------------------------------
__device__ __forceinline__ int pix_class(const float l[7]) {
    float e0 = __expf(l[0]);
    float e1 = __expf(l[1]);
    float e2 = __expf(l[2]);
    float e3 = __expf(l[3]);
    float e4 = __expf(l[4]);
    float e5 = __expf(l[5]);
    float e6 = __expf(l[6]);
    float den = ((e0 + e1) + (e2 + e3)) + ((e4 + e5) + e6);
    float num = e1;
    num = fmaf(2.0f, e2, num);
    num = fmaf(3.0f, e3, num);
    num = fmaf(4.0f, e4, num);
    num = fmaf(5.0f, e5, num);
    num = fmaf(6.0f, e6, num);
    // num/den in [0,6]; truncation == floor for non-negative values.
    float r = __fdividef(num, den);
    return (int)r;
}

__global__ __launch_bounds__(160) void k_rowstats(const float* __restrict__ logits) {
    const int row  = blockIdx.x;
    const int b    = blockIdx.y;
    const int t    = threadIdx.x;
    const int lane = t & 31;
    const int warp = t >> 5;
    const int col0 = t << 2;   // 4 pixels per thread

    float4 v[NCLS];
#pragma unroll
    for (int c = 0; c < NCLS; c++) {
        const float* p = logits + (((size_t)b * NCLS + c) * HH + row) * WW + col0;
        v[c] = *reinterpret_cast<const float4*>(p);
    }

    int k0, k1, k2, k3;
    {
        float l[7];
#pragma unroll
        for (int c = 0; c < NCLS; c++) l[c] = v[c].x;
        k0 = pix_class(l);
#pragma unroll
        for (int c = 0; c < NCLS; c++) l[c] = v[c].y;
        k1 = pix_class(l);
#pragma unroll
        for (int c = 0; c < NCLS; c++) l[c] = v[c].z;
        k2 = pix_class(l);
#pragma unroll
        for (int c = 0; c < NCLS; c++) l[c] = v[c].w;
        k3 = pix_class(l);
    }

    // One-hot bitboard: byte j holds (1 << class_of_pixel_j).
    const unsigned B = (1u << k0) | (1u << (k1 + 8)) | (1u << (k2 + 16)) | (1u << (k3 + 24));

    unsigned mypk = 0;  // lane c-1 keeps class c's packed stats

#pragma unroll
    for (int c = 1; c <= 6; c++) {
        unsigned m = (B >> c) & 0x01010101u;  // bit 8*j set iff pixel j is class c
        int cnt = __popc(m);
        int mnl = m ? col0 + ((__ffs(m) - 1) >> 3) : 0x7fffffff;
        int mxl = m ? col0 + ((31 - __clz(m)) >> 3) : -1;
        int wmn = __reduce_min_sync(0xffffffffu, mnl);
        int wmx = __reduce_max_sync(0xffffffffu, mxl);
        int wct = __reduce_add_sync(0xffffffffu, cnt);
        if (lane == c - 1) {
            mypk = (wct == 0) ? 0u
                 : ((unsigned)wmn | ((unsigned)wmx << 10) | ((unsigned)wct << 20));
        }
    }

    if (lane < 6) {
        g_row5[(((b * 6 + lane) * HH) + row) * 8 + warp] = mypk;
    }
}

// -------------------------------------------------------------------------
// Kernel 2: one 32-thread block per segment (96 blocks). Lane owns 12
// contiguous rows; all 24 uint4 loads issued fully unrolled up-front
// (MLP=24, one DRAM round-trip), then fold 5 warp-slots per row, ordered
// in-lane merge, 5-step ordered warp tree. No smem, no barriers.
// Within-row contribution telescopes to (max-min); merging adjacent
// segments adds |d_first(right) - d_last(left)| with d = col - row.
// -------------------------------------------------------------------------
__global__ __launch_bounds__(32) void k_combine() {
    const int seg  = blockIdx.x;
    const int lane = threadIdx.x;
    const int r0   = lane * 12;   // rows [r0, r0+12); 12*32=384 covers HH=368

    uint4 ua[12], ub[12];
#pragma unroll
    for (int i = 0; i < 12; i++) {
        const int r = r0 + i;
        if (r < HH) {
            const uint4* p = reinterpret_cast<const uint4*>(&g_row5[(seg * HH + r) * 8]);
            ua[i] = p[0];
            ub[i] = p[1];
        } else {
            ua[i] = make_uint4(0, 0, 0, 0);
            ub[i] = make_uint4(0, 0, 0, 0);
        }
    }

    int valid = 0, cnt = 0, S = 0;
    int fcol = 0, frow = 0, lcol = 0, lrow = 0;

#pragma unroll
    for (int i = 0; i < 12; i++) {
        const int r = r0 + i;
        unsigned pks[5] = {ua[i].x, ua[i].y, ua[i].z, ua[i].w, ub[i].x};
        int rc = 0, mnv = 0x7fffffff, mxv = -1;
#pragma unroll
        for (int s = 0; s < 5; s++) {
            unsigned pk = pks[s];
            int c = pk >> 20;
            if (c) {
                rc += c;
                mnv = min(mnv, (int)(pk & 1023));
                mxv = max(mxv, (int)((pk >> 10) & 1023));
            }
        }
        if (rc) {
            if (valid) {
                S += abs((mnv - r) - (lcol - lrow));
            } else {
                fcol = mnv; frow = r; valid = 1;
            }
            S += mxv - mnv;
            lcol = mxv; lrow = r; cnt += rc;
        }
    }

    // Ordered warp tree: lane absorbs the segment from lane+off (its right).
#pragma unroll
    for (int off = 1; off < 32; off <<= 1) {
        int ov  = __shfl_down_sync(0xffffffffu, valid, off);
        int oc  = __shfl_down_sync(0xffffffffu, cnt, off);
        int oS  = __shfl_down_sync(0xffffffffu, S, off);
        int ofc = __shfl_down_sync(0xffffffffu, fcol, off);
        int ofr = __shfl_down_sync(0xffffffffu, frow, off);
        int olc = __shfl_down_sync(0xffffffffu, lcol, off);
        int olr = __shfl_down_sync(0xffffffffu, lrow, off);
        if ((lane & (2 * off - 1)) == 0 && ov) {
            if (valid) {
                S += oS + abs((ofc - ofr) - (lcol - lrow));
            } else {
                S = oS; fcol = ofc; frow = ofr; valid = 1;
            }
            cnt += oc;
            lcol = olc; lrow = olr;
        }
    }

    if (lane == 0) {
        float loss = 0.0f;
        if (cnt >= 2) {
            loss = ((float)S / (float)(cnt - 1)) / (float)(cnt + 1);
        }
        g_part[seg] = loss;
    }
}

// -------------------------------------------------------------------------
// Kernel 3: deterministic sum of the 96 partials -> d_out[0].
// -------------------------------------------------------------------------
__global__ __launch_bounds__(128) void k_final(float* __restrict__ out) {
    const int t = threadIdx.x;
    float v = (t < NSEG) ? g_part[t] : 0.0f;
#pragma unroll
    for (int off = 16; off > 0; off >>= 1)
        v += __shfl_down_sync(0xffffffffu, v, off);
    __shared__ float sh[4];
    if ((t & 31) == 0) sh[t >> 5] = v;
    __syncthreads();
    if (t == 0) out[0] = (sh[0] + sh[1]) + (sh[2] + sh[3]);
}

extern "C" void kernel_launch(void* const* d_in, const int* in_sizes, int n_in,
                              void* d_out, int out_size) {
    const float* logits = (const float*)d_in[0];
    // d_in[1] (labels) is unused by the reference computation.
    dim3 g1(HH, BATCH);
    k_rowstats<<<g1, 160>>>(logits);
    k_combine<<<NSEG, 32>>>();
    k_final<<<1, 128>>>((float*)d_out);
}